// round 3
// baseline (speedup 1.0000x reference)
#include <cuda_runtime.h>

#define SEQ   256
#define BATCH 64
#define EMBD  512
#define HID   1024
#define GATE  (4*HID)      // 4096
#define VOCAB 128
#define NCTA  128
#define NTHR  128
#define BH    (BATCH*HID)  // 65536

// -------- persistent scratch (static device globals; no runtime allocs) ------
__device__ float g_XW[(size_t)SEQ * BATCH * GATE];   // 256 MB: per-step input-proj gates
__device__ float g_ys0[(size_t)SEQ * BH];            // 64 MB: layer-0 outputs (all steps)
__device__ float g_h1[2 * BH];                       // layer-1 h double buffer
__device__ unsigned g_barGen;                        // grid barrier generation (monotonic)
__device__ unsigned g_barCnt;                        // grid barrier arrival counter

// -------- grid-wide barrier (all 128 CTAs co-resident: 128 <= 148 SMs) -------
__device__ __forceinline__ void gridbar(unsigned &gen) {
    __syncthreads();
    if (threadIdx.x == 0) {
        const unsigned target = gen + 1u;
        __threadfence();                               // release our writes
        unsigned arrived = atomicAdd(&g_barCnt, 1u);
        if (arrived == (unsigned)(gridDim.x - 1)) {
            g_barCnt = 0u;
            __threadfence();
            atomicExch(&g_barGen, target);
        } else {
            while ((int)(*((volatile unsigned *)&g_barGen) - target) < 0) { }
        }
        __threadfence();                               // acquire others' writes
    }
    gen++;
    __syncthreads();
}

// -------- big input-projection GEMM --------------------------------------
// C[m][n] = sum_k A(m,k) * W[n][k] + bias[n],  m < SEQ*BATCH, n < GATE.
// A(m,k) = emb[x[m]][k]  (phase A, xidx != nullptr)  or  Adir[m*Kdim+k].
// Tile 64x64, K-tile 32, 128 threads, 4x8 micro-tile per thread.
__device__ void gemm_phase(const int *xidx, const float *embt, const float *Adir,
                           int Kdim, const float *W, const float *bias,
                           float *C, float *sm)
{
    const int tid = threadIdx.x;
    float *As = sm;               // [64][36]
    float *Bs = sm + 64 * 36;     // [64][36]
    const int numTiles = (SEQ * BATCH / 64) * (GATE / 64);   // 256*64 = 16384

    for (int tile = blockIdx.x; tile < numTiles; tile += NCTA) {
        const int mt = tile >> 6;      // 0..255
        const int nt = tile & 63;      // 0..63
        float acc[4][8];
#pragma unroll
        for (int rr = 0; rr < 4; rr++)
#pragma unroll
            for (int nn = 0; nn < 8; nn++) acc[rr][nn] = 0.f;

        for (int k0 = 0; k0 < Kdim; k0 += 32) {
            __syncthreads();
            // stage A (64x32) and B (64x32) as float4: 512 float4 each / 128 thr
#pragma unroll
            for (int i = 0; i < 4; i++) {
                int idx = tid + i * NTHR;          // 0..511
                int r = idx >> 3, k4 = idx & 7;    // row, float4-col
                int m = mt * 64 + r;
                float4 av;
                if (xidx) {
                    av = *(const float4 *)&embt[(size_t)xidx[m] * EMBD + k0 + 4 * k4];
                } else {
                    av = *(const float4 *)&Adir[(size_t)m * Kdim + k0 + 4 * k4];
                }
                *(float4 *)&As[r * 36 + 4 * k4] = av;
                int n = nt * 64 + r;
                *(float4 *)&Bs[r * 36 + 4 * k4] =
                    *(const float4 *)&W[(size_t)n * Kdim + k0 + 4 * k4];
            }
            __syncthreads();
#pragma unroll
            for (int kk = 0; kk < 8; kk++) {
                float4 a[4], b[8];
#pragma unroll
                for (int rr = 0; rr < 4; rr++)
                    a[rr] = *(const float4 *)&As[((tid >> 3) + 16 * rr) * 36 + kk * 4];
#pragma unroll
                for (int nn = 0; nn < 8; nn++)
                    b[nn] = *(const float4 *)&Bs[((tid & 7) + 8 * nn) * 36 + kk * 4];
#pragma unroll
                for (int rr = 0; rr < 4; rr++)
#pragma unroll
                    for (int nn = 0; nn < 8; nn++)
                        acc[rr][nn] += a[rr].x * b[nn].x + a[rr].y * b[nn].y +
                                       a[rr].z * b[nn].z + a[rr].w * b[nn].w;
            }
        }
        // write back (+bias)
#pragma unroll
        for (int rr = 0; rr < 4; rr++) {
            int m = mt * 64 + (tid >> 3) + 16 * rr;
#pragma unroll
            for (int nn = 0; nn < 8; nn++) {
                int n = nt * 64 + (tid & 7) + 8 * nn;
                C[(size_t)m * GATE + n] = acc[rr][nn] + bias[n];
            }
        }
    }
}

// -------- LSTM recurrence for one layer ----------------------------------
// CTA owns hidden units [u0, u0+8) -> 32 gate rows of Whh cached in smem.
// Per step: gates[64][32] = XW[t] + h_prev @ Whh_sliceT, then pointwise update.
__device__ void lstm_layer(const float *xw, const float *h0L, const float *c0L,
                           const float *Whh, int layer,
                           float *outH, float *outC, float *sm, unsigned &gen)
{
    const int tid = threadIdx.x;
    const int u0 = blockIdx.x * 8;
    float *Ws = sm;                      // [32][1028]
    float *Hs = sm + 32 * 1028;          // [64][132]
    float *Gs = Hs + 64 * 132;           // [64][32]

    // load Whh slice (32 rows x 1024) as float4: 8192 float4 / 128 thr
#pragma unroll 4
    for (int i = 0; i < 64; i++) {
        int idx = tid + i * NTHR;            // 0..8191
        int j = idx >> 8, k4 = idx & 255;    // gate-row j, float4 col
        int r = (j >> 3) * HID + u0 + (j & 7);
        *(float4 *)&Ws[j * 1028 + 4 * k4] =
            *(const float4 *)&Whh[(size_t)r * HID + 4 * k4];
    }
    // c state in registers: pair p = tid + 128*i -> (b=p/8, u=p%8)
    float creg[4];
#pragma unroll
    for (int i = 0; i < 4; i++) {
        int p = tid + i * NTHR;
        int b = p >> 3, u = p & 7;
        creg[i] = c0L[b * HID + u0 + u];
    }
    __syncthreads();

    for (int t = 0; t < SEQ; t++) {
        const float *src;
        float *dst;
        if (layer == 0) {
            src = t ? (g_ys0 + (size_t)(t - 1) * BH) : h0L;
            dst = g_ys0 + (size_t)t * BH;
        } else {
            src = t ? (g_h1 + (size_t)((t - 1) & 1) * BH) : h0L;
            dst = g_h1 + (size_t)(t & 1) * BH;
        }

        // init gate accumulators from precomputed XW (bias already folded in)
        float acc[4][4];
        const float *xwt = xw + (size_t)t * BATCH * GATE;
#pragma unroll
        for (int bb = 0; bb < 4; bb++) {
            int b = (tid >> 3) + 16 * bb;
#pragma unroll
            for (int jj = 0; jj < 4; jj++)
                acc[bb][jj] = xwt[(size_t)b * GATE + jj * HID + u0 + (tid & 7)];
        }

        for (int k0 = 0; k0 < HID; k0 += 128) {
            __syncthreads();
            // stage h tile [64][128] as float4: 2048 float4 / 128 thr
#pragma unroll 4
            for (int i = 0; i < 16; i++) {
                int idx = tid + i * NTHR;        // 0..2047
                int b = idx >> 5, k4 = idx & 31;
                *(float4 *)&Hs[b * 132 + 4 * k4] =
                    *(const float4 *)&src[b * HID + k0 + 4 * k4];
            }
            __syncthreads();
#pragma unroll 2
            for (int kk = 0; kk < 32; kk++) {
                float4 hv[4], wv[4];
#pragma unroll
                for (int bb = 0; bb < 4; bb++)
                    hv[bb] = *(const float4 *)&Hs[((tid >> 3) + 16 * bb) * 132 + kk * 4];
#pragma unroll
                for (int jj = 0; jj < 4; jj++)
                    wv[jj] = *(const float4 *)&Ws[((tid & 7) + 8 * jj) * 1028 + k0 + kk * 4];
#pragma unroll
                for (int bb = 0; bb < 4; bb++)
#pragma unroll
                    for (int jj = 0; jj < 4; jj++)
                        acc[bb][jj] += hv[bb].x * wv[jj].x + hv[bb].y * wv[jj].y +
                                       hv[bb].z * wv[jj].z + hv[bb].w * wv[jj].w;
            }
        }
        // gates -> smem for pointwise stage
#pragma unroll
        for (int bb = 0; bb < 4; bb++) {
            int b = (tid >> 3) + 16 * bb;
#pragma unroll
            for (int jj = 0; jj < 4; jj++)
                Gs[b * 32 + (tid & 7) + 8 * jj] = acc[bb][jj];
        }
        __syncthreads();
        // pointwise LSTM cell update; thread owns same 4 (b,u) pairs every step
#pragma unroll
        for (int i = 0; i < 4; i++) {
            int p = tid + i * NTHR;
            int b = p >> 3, u = p & 7;
            float ig = Gs[b * 32 + u];
            float fg = Gs[b * 32 + 8 + u];
            float gg = Gs[b * 32 + 16 + u];
            float og = Gs[b * 32 + 24 + u];
            ig = 1.f / (1.f + __expf(-ig));
            fg = 1.f / (1.f + __expf(-fg));
            og = 1.f / (1.f + __expf(-og));
            gg = tanhf(gg);
            float c = fg * creg[i] + ig * gg;
            creg[i] = c;
            float h = og * tanhf(c);
            dst[b * HID + u0 + u] = h;
            if (t == SEQ - 1) {
                outH[b * HID + u0 + u] = h;
                outC[b * HID + u0 + u] = c;
            }
        }
        gridbar(gen);   // all CTAs must see new h before next step
    }
}

// -------- final FC: logits[64][128] = h_last @ WfcT + bfc ------------------
__device__ void fc_phase(const float *hlast, const float *Wfc, const float *bfc,
                         float *out)
{
    const int v = blockIdx.x;          // 128 CTAs == VOCAB
    const int tid = threadIdx.x;
    if (tid < BATCH) {
        float s = 0.f;
#pragma unroll 4
        for (int k = 0; k < HID; k += 4) {
            float4 hh = *(const float4 *)&hlast[tid * HID + k];
            float4 ww = *(const float4 *)&Wfc[(size_t)v * HID + k];
            s += hh.x * ww.x + hh.y * ww.y + hh.z * ww.z + hh.w * ww.w;
        }
        out[tid * VOCAB + v] = s + bfc[v];
    }
}

// -------- the single persistent kernel ------------------------------------
__global__ void __launch_bounds__(NTHR, 1) lstm_all_kernel(
    const int *x, const float *h0, const float *c0, const float *embt,
    const float *Wih0, const float *Whh0, const float *b0,
    const float *Wih1, const float *Whh1, const float *b1,
    const float *Wfc, const float *bfc, float *out)
{
    extern __shared__ float sm[];
    unsigned gen = *((volatile unsigned *)&g_barGen);   // stable until 1st barrier

    // Phase A: XW0 = emb[x] @ Wih0^T + b0
    gemm_phase(x, embt, nullptr, EMBD, Wih0, b0, g_XW, sm);
    gridbar(gen);

    // Layer 0 recurrence (writes all ys0; finals -> d_out)
    lstm_layer(g_XW, h0, c0, Whh0, 0,
               out + VOCAB * BATCH,                 // h layer 0
               out + VOCAB * BATCH + 2 * BH,        // c layer 0
               sm, gen);

    // Phase B: XW1 = ys0 @ Wih1^T + b1  (overwrites g_XW)
    gemm_phase(nullptr, nullptr, g_ys0, HID, Wih1, b1, g_XW, sm);
    gridbar(gen);

    // Layer 1 recurrence
    lstm_layer(g_XW, h0 + BH, c0 + BH, Whh1, 1,
               out + VOCAB * BATCH + BH,            // h layer 1
               out + VOCAB * BATCH + 2 * BH + BH,   // c layer 1
               sm, gen);

    // FC head (h_last for t=255 lives in g_h1 buffer 1)
    fc_phase(g_h1 + BH, Wfc, bfc, out);
}

extern "C" void kernel_launch(void *const *d_in, const int *in_sizes, int n_in,
                              void *d_out, int out_size)
{
    const int   *x    = (const int *)d_in[0];
    const float *h0   = (const float *)d_in[1];
    const float *c0   = (const float *)d_in[2];
    const float *embt = (const float *)d_in[3];
    const float *Wih0 = (const float *)d_in[4];
    const float *Whh0 = (const float *)d_in[5];
    const float *b0   = (const float *)d_in[6];
    const float *Wih1 = (const float *)d_in[7];
    const float *Whh1 = (const float *)d_in[8];
    const float *b1   = (const float *)d_in[9];
    const float *Wfc  = (const float *)d_in[10];
    const float *bfc  = (const float *)d_in[11];
    float *out = (float *)d_out;

    // recurrence smem: 32*1028 + 64*132 + 64*32 floats = 173,568 B
    const int smemBytes = (32 * 1028 + 64 * 132 + 64 * 32) * (int)sizeof(float);
    cudaFuncSetAttribute(lstm_all_kernel,
                         cudaFuncAttributeMaxDynamicSharedMemorySize, smemBytes);
    lstm_all_kernel<<<NCTA, NTHR, smemBytes>>>(x, h0, c0, embt, Wih0, Whh0, b0,
                                               Wih1, Whh1, b1, Wfc, bfc, out);
}

// round 5
// speedup vs baseline: 2.3177x; 2.3177x over previous
#include <cuda_runtime.h>
#include <cstdint>

#define SEQ 256
#define BATCH 64
#define EMBD 512
#define HID 1024
#define GATE 4096
#define VOCAB 128
#define NCTA 128
#define NTHR 128
#define BH (BATCH*HID)

// smem layout (float indices)
#define AF_F 0            // recurrence A-fragments: 8192 uint4 = 32768 floats (128KB)
#define BSR_F 32768       // recurrence B stage: 64 x 132 = 8448 floats
#define GS_F  (32768+8448) // gate scratch: 32 x 68 = 2176 floats
#define SMEM_FLOATS (32768+8448+2176)
// phases reuse: AS at 0 (128x132=16896), BS2 at 16896 (64x132=8448)

__device__ float g_XW[(size_t)SEQ*BATCH*GATE];
__device__ float g_ys0[(size_t)SEQ*BH];
__device__ float g_h1[2*BH];
__device__ unsigned g_barGen, g_barCnt;

__device__ __forceinline__ uint32_t tf(float f){
    uint32_t r; asm("cvt.rna.tf32.f32 %0, %1;":"=r"(r):"f"(f)); return r;
}
__device__ __forceinline__ uint4 tf4(float4 v){
    uint4 o; o.x=tf(v.x); o.y=tf(v.y); o.z=tf(v.z); o.w=tf(v.w); return o;
}
__device__ __forceinline__ void mma8(float &d0,float &d1,float &d2,float &d3,
                                     uint4 a, uint32_t b0, uint32_t b1){
    asm volatile("mma.sync.aligned.m16n8k8.row.col.f32.tf32.tf32.f32 "
                 "{%0,%1,%2,%3},{%4,%5,%6,%7},{%8,%9},{%0,%1,%2,%3};"
                 :"+f"(d0),"+f"(d1),"+f"(d2),"+f"(d3)
                 :"r"(a.x),"r"(a.y),"r"(a.z),"r"(a.w),"r"(b0),"r"(b1));
}

__device__ __forceinline__ void gridbar(unsigned &gen){
    __syncthreads();
    if(threadIdx.x==0){
        const unsigned target=gen+1u;
        __threadfence();
        unsigned a=atomicAdd(&g_barCnt,1u);
        if(a==(unsigned)(gridDim.x-1)){ g_barCnt=0u; __threadfence(); atomicExch(&g_barGen,target); }
        else { while((int)(*((volatile unsigned*)&g_barGen)-target)<0){} }
        __threadfence();
    }
    gen++; __syncthreads();
}

// ---- phase GEMM: C[token][gate] = A(token,:) . W(gate,:) + bias ----------
// tile: M=128 tokens x N=64 gates; warps 2x2 of (64 x 32); K chunks of 128.
__device__ void phase_gemm(const int *xidx,const float *emb,const float *Adir,
                           int Kdim,const float *W,const float *bias,float *C,
                           float *sm){
    const int tid=threadIdx.x, lane=tid&31, wid=tid>>5;
    const int wm=wid&1, wn=wid>>1;
    uint32_t *AS=(uint32_t*)sm;          // [128][132] tf32 bits
    uint32_t *BS=(uint32_t*)(sm+16896);  // [64][132]
    const int g=lane>>2, tg=lane&3;

    for(int tile=blockIdx.x; tile<128*64; tile+=NCTA){
        const int mt=tile>>6, ntg=tile&63;
        const int m0=mt*128, n0=ntg*64;
        float d[4][4][4];
#pragma unroll
        for(int a=0;a<4;a++)
#pragma unroll
        for(int b=0;b<4;b++)
#pragma unroll
        for(int c=0;c<4;c++) d[a][b][c]=0.f;

        for(int kc=0; kc<Kdim/128; kc++){
            __syncthreads();
            // stage A: 128 tokens x 128 k
#pragma unroll
            for(int i=0;i<32;i++){
                int idx=tid+i*NTHR, r=idx>>5, q=idx&31;
                const float *src = xidx
                    ? emb+(size_t)xidx[m0+r]*EMBD + kc*128 + 4*q
                    : Adir+(size_t)(m0+r)*Kdim + kc*128 + 4*q;
                *(uint4*)&AS[r*132+4*q]=tf4(*(const float4*)src);
            }
            // stage B: 64 gate rows x 128 k
#pragma unroll
            for(int i=0;i<16;i++){
                int idx=tid+i*NTHR, r=idx>>5, q=idx&31;
                float4 v=*(const float4*)&W[(size_t)(n0+r)*Kdim + kc*128 + 4*q];
                *(uint4*)&BS[r*132+4*q]=tf4(v);
            }
            __syncthreads();
#pragma unroll 4
            for(int ks=0; ks<16; ks++){
                const int kk=ks*8+tg;
                uint4 af[4]; uint32_t b0[4],b1[4];
#pragma unroll
                for(int mi=0;mi<4;mi++){
                    int m=wm*64+mi*16+g;
                    af[mi].x=AS[m*132+kk];     af[mi].y=AS[(m+8)*132+kk];
                    af[mi].z=AS[m*132+kk+4];   af[mi].w=AS[(m+8)*132+kk+4];
                }
#pragma unroll
                for(int nt=0;nt<4;nt++){
                    int n=wn*32+nt*8+g;
                    b0[nt]=BS[n*132+ks*8+tg]; b1[nt]=BS[n*132+ks*8+tg+4];
                }
#pragma unroll
                for(int mi=0;mi<4;mi++)
#pragma unroll
                for(int nt=0;nt<4;nt++)
                    mma8(d[mi][nt][0],d[mi][nt][1],d[mi][nt][2],d[mi][nt][3],
                         af[mi],b0[nt],b1[nt]);
            }
        }
        // epilogue
#pragma unroll
        for(int mi=0;mi<4;mi++){
            int m=m0+wm*64+mi*16+g;
#pragma unroll
            for(int nt=0;nt<4;nt++){
                int n=n0+wn*32+nt*8+2*tg;
                float2 v0={d[mi][nt][0]+bias[n], d[mi][nt][1]+bias[n+1]};
                float2 v1={d[mi][nt][2]+bias[n], d[mi][nt][3]+bias[n+1]};
                *(float2*)&C[(size_t)m*GATE+n]=v0;
                *(float2*)&C[(size_t)(m+8)*GATE+n]=v1;
            }
        }
    }
}

// ---- LSTM recurrence: CTA owns 8 hidden units (32 gate rows), N=64 batch --
__device__ void lstm_layer(const float *xw_all,const float *h0L,const float *c0L,
                           const float *Whh,int layer,float *outH,float *outC,
                           float *sm,unsigned &gen){
    const int tid=threadIdx.x, lane=tid&31, wid=tid>>5;
    const int wm=wid&1, wn=wid>>1;
    const int u0=blockIdx.x*8;
    const int g=lane>>2, tg=lane&3;
    uint4 *AF=(uint4*)(sm+AF_F);            // [128 ks][2 mt][32 lane]
    uint32_t *BS=(uint32_t*)(sm+BSR_F);     // [64][132]
    float *GS=sm+GS_F;                      // [32][68]

    // pre-gather Whh slice into fragment-linear tf32 layout (once per layer)
    for(int idx=tid; idx<8192; idx+=NTHR){
        int ks=idx>>6, mt=(idx>>5)&1, l=idx&31;
        int m=mt*16+(l>>2), k=ks*8+(l&3);
        // local gate row m -> Whh global row (m>>3)*HID + u0 + (m&7)
        int r0=((m  )>>3)*HID+u0+((m  )&7);
        int r1=((m+8)>>3)*HID+u0+((m+8)&7);
        uint4 v;
        v.x=tf(Whh[(size_t)r0*HID+k]);
        v.y=tf(Whh[(size_t)r1*HID+k]);
        v.z=tf(Whh[(size_t)r0*HID+k+4]);
        v.w=tf(Whh[(size_t)r1*HID+k+4]);
        AF[(ks*2+mt)*32+l]=v;
    }
    float cst[4];
#pragma unroll
    for(int i=0;i<4;i++){
        int p=tid+i*NTHR, u=p>>6, b=p&63;
        cst[i]=c0L[b*HID+u0+u];
    }
    __syncthreads();

    for(int t=0;t<SEQ;t++){
        const float *hsrc=(t==0)?h0L:(layer==0? g_ys0+(size_t)(t-1)*BH
                                              : g_h1+(size_t)((t-1)&1)*BH);
        float d[4][4];
#pragma unroll
        for(int a=0;a<4;a++)
#pragma unroll
        for(int b=0;b<4;b++) d[a][b]=0.f;

        for(int c=0;c<8;c++){
            __syncthreads();
            // stage h chunk: 64 batch x 128 k
#pragma unroll
            for(int i=0;i<16;i++){
                int idx=tid+i*NTHR, r=idx>>5, q=idx&31;
                float4 v=*(const float4*)&hsrc[(size_t)r*HID + c*128 + 4*q];
                *(uint4*)&BS[r*132+4*q]=tf4(v);
            }
            __syncthreads();
#pragma unroll 4
            for(int ks2=0; ks2<16; ks2++){
                const int ks=c*16+ks2;
                uint4 af=AF[(ks*2+wm)*32+lane];
                uint32_t b0[4],b1[4];
#pragma unroll
                for(int nt=0;nt<4;nt++){
                    int n=wn*32+nt*8+g;
                    b0[nt]=BS[n*132+ks2*8+tg];
                    b1[nt]=BS[n*132+ks2*8+tg+4];
                }
#pragma unroll
                for(int nt=0;nt<4;nt++)
                    mma8(d[nt][0],d[nt][1],d[nt][2],d[nt][3],af,b0[nt],b1[nt]);
            }
        }
        // D -> gate scratch
#pragma unroll
        for(int nt=0;nt<4;nt++){
            int m=wm*16+g, n=wn*32+nt*8+2*tg;
            GS[m*68+n]=d[nt][0];     GS[m*68+n+1]=d[nt][1];
            GS[(m+8)*68+n]=d[nt][2]; GS[(m+8)*68+n+1]=d[nt][3];
        }
        __syncthreads();
        // pointwise
        const float *xwt=xw_all+(size_t)t*BATCH*GATE;
        float *dst=(layer==0)? g_ys0+(size_t)t*BH : g_h1+(size_t)(t&1)*BH;
#pragma unroll
        for(int i=0;i<4;i++){
            int p=tid+i*NTHR, u=p>>6, b=p&63;
            const float *xwb=xwt+(size_t)b*GATE+u0+u;
            float ig=GS[(0*8+u)*68+b]+xwb[0*HID];
            float fg=GS[(1*8+u)*68+b]+xwb[1*HID];
            float gg=GS[(2*8+u)*68+b]+xwb[2*HID];
            float og=GS[(3*8+u)*68+b]+xwb[3*HID];
            ig=1.f/(1.f+__expf(-ig));
            fg=1.f/(1.f+__expf(-fg));
            og=1.f/(1.f+__expf(-og));
            gg=tanhf(gg);
            float cc=fg*cst[i]+ig*gg;
            cst[i]=cc;
            float h=og*tanhf(cc);
            dst[b*HID+u0+u]=h;
            if(t==SEQ-1){ outH[b*HID+u0+u]=h; outC[b*HID+u0+u]=cc; }
        }
        gridbar(gen);
    }
}

__device__ void fc_phase(const float *hlast,const float *Wfc,const float *bfc,float *out){
    const int v=blockIdx.x, tid=threadIdx.x;
    if(tid<BATCH){
        float s=0.f;
#pragma unroll 4
        for(int k=0;k<HID;k+=4){
            float4 hh=*(const float4*)&hlast[tid*HID+k];
            float4 ww=*(const float4*)&Wfc[(size_t)v*HID+k];
            s+=hh.x*ww.x+hh.y*ww.y+hh.z*ww.z+hh.w*ww.w;
        }
        out[tid*VOCAB+v]=s+bfc[v];
    }
}

__global__ void __launch_bounds__(NTHR,1) lstm_all_kernel(
    const int *x,const float *h0,const float *c0,const float *embt,
    const float *Wih0,const float *Whh0,const float *b0,
    const float *Wih1,const float *Whh1,const float *b1,
    const float *Wfc,const float *bfc,float *out){
    extern __shared__ float sm[];
    unsigned gen=*((volatile unsigned*)&g_barGen);

    phase_gemm(x,embt,nullptr,EMBD,Wih0,b0,g_XW,sm);
    gridbar(gen);
    lstm_layer(g_XW,h0,c0,Whh0,0,
               out+VOCAB*BATCH, out+VOCAB*BATCH+2*BH, sm,gen);
    gridbar(gen);
    phase_gemm(nullptr,nullptr,g_ys0,HID,Wih1,b1,g_XW,sm);
    gridbar(gen);
    lstm_layer(g_XW,h0+BH,c0+BH,Whh1,1,
               out+VOCAB*BATCH+BH, out+VOCAB*BATCH+3*BH, sm,gen);
    fc_phase(g_h1+BH,Wfc,bfc,out);
}

extern "C" void kernel_launch(void *const *d_in,const int *in_sizes,int n_in,
                              void *d_out,int out_size){
    const int   *x   =(const int*)d_in[0];
    const float *h0  =(const float*)d_in[1];
    const float *c0  =(const float*)d_in[2];
    const float *embt=(const float*)d_in[3];
    const float *Wih0=(const float*)d_in[4];
    const float *Whh0=(const float*)d_in[5];
    const float *b0  =(const float*)d_in[6];
    const float *Wih1=(const float*)d_in[7];
    const float *Whh1=(const float*)d_in[8];
    const float *b1  =(const float*)d_in[9];
    const float *Wfc =(const float*)d_in[10];
    const float *bfc =(const float*)d_in[11];
    float *out=(float*)d_out;
    const int smemBytes=SMEM_FLOATS*(int)sizeof(float);   // 173,568 B
    cudaFuncSetAttribute(lstm_all_kernel,
                         cudaFuncAttributeMaxDynamicSharedMemorySize,smemBytes);
    lstm_all_kernel<<<NCTA,NTHR,smemBytes>>>(x,h0,c0,embt,Wih0,Whh0,b0,
                                             Wih1,Whh1,b1,Wfc,bfc,out);
}